// round 15
// baseline (speedup 1.0000x reference)
#include <cuda_runtime.h>
#include <cuda_fp16.h>
#include <mma.h>
#include <cstdint>

using namespace nvcuda;

#define NN   100000
#define CC   128
#define EMAX 1600000
#define NB   ((NN + 255) / 256)        // 391 scan blocks

// ---------------- scratch (static device globals) --------------------------
__device__ __align__(16) __half g_ah[(size_t)NN * CC];   // half agg buffer
__device__ __align__(16) __half g_zh[(size_t)NN * 40];   // layer-3 z (half)
__device__ __align__(16) __half g_hx[(size_t)NN * CC];   // half features
__device__ __align__(16) int2   g_edge[EMAX];            // packed (src, w-bits)
__device__ int   g_cnt[NN];
__device__ int   g_rowstart[NN];       // block-local exclusive prefix
__device__ int   g_cursor[NN];         // fill counters (zeroed in k_cvt)
__device__ int   g_bsum[NB];
__device__ int   g_boff[NB];           // block offsets (exclusive)
__device__ double g_sum[2][CC];
__device__ double g_sumsq[2][CC];

// ---------------- merged init + feat->half conversion ----------------------
__global__ void __launch_bounds__(256) k_cvt(const float* __restrict__ feat)
{
    size_t i = (size_t)blockIdx.x * 256 + threadIdx.x;   // float4 index
    if (i < (size_t)NN * (CC / 4)) {
        float4 v = ((const float4*)feat)[i];
        __half2 h0 = __floats2half2_rn(v.x, v.y);
        __half2 h1 = __floats2half2_rn(v.z, v.w);
        uint2 p;
        p.x = *(unsigned*)&h0;
        p.y = *(unsigned*)&h1;
        ((uint2*)g_hx)[i] = p;
    }
    int j = blockIdx.x * 256 + threadIdx.x;
    if (j < NN) { g_cnt[j] = 0; g_cursor[j] = 0; }
    if (blockIdx.x == 0 && threadIdx.x < CC) {
        g_sum[0][threadIdx.x] = 0.0;  g_sumsq[0][threadIdx.x] = 0.0;
        g_sum[1][threadIdx.x] = 0.0;  g_sumsq[1][threadIdx.x] = 0.0;
    }
}

__global__ void __launch_bounds__(256) k_hist(const int* __restrict__ dst, int E)
{
    int e = blockIdx.x * 256 + threadIdx.x;
    if (e < E) atomicAdd(&g_cnt[dst[e]], 1);
}

__global__ void __launch_bounds__(256) k_scan1()
{
    __shared__ int sm[256];
    int tid = threadIdx.x;
    int i = blockIdx.x * 256 + tid;
    int c = (i < NN) ? g_cnt[i] : 0;
    sm[tid] = c;
    __syncthreads();
    #pragma unroll
    for (int off = 1; off < 256; off <<= 1) {
        int v = (tid >= off) ? sm[tid - off] : 0;
        __syncthreads();
        sm[tid] += v;
        __syncthreads();
    }
    if (i < NN) g_rowstart[i] = sm[tid] - c;       // block-LOCAL exclusive
    if (tid == 255) g_bsum[blockIdx.x] = sm[255];
}

__global__ void __launch_bounds__(512) k_scan2()
{
    __shared__ int sm[512];
    int tid = threadIdx.x;
    int v = (tid < NB) ? g_bsum[tid] : 0;
    sm[tid] = v;
    __syncthreads();
    #pragma unroll
    for (int off = 1; off < 512; off <<= 1) {
        int u = (tid >= off) ? sm[tid - off] : 0;
        __syncthreads();
        sm[tid] += u;
        __syncthreads();
    }
    if (tid < NB) g_boff[tid] = sm[tid] - v;       // exclusive block offset
}

__global__ void __launch_bounds__(256) k_fill(const int* __restrict__ src,
                                              const int* __restrict__ dst,
                                              const float* __restrict__ ew,
                                              int E)
{
    int e = blockIdx.x * 256 + threadIdx.x;
    if (e < E) {
        int d = dst[e];
        int base = g_rowstart[d] + g_boff[d >> 8];
        int slot = base + atomicAdd(&g_cursor[d], 1);
        g_edge[slot] = make_int2(src[e], __float_as_int(ew[e]));
    }
}

// ---------------- gather aggregation: warp per node, 2 edges per pass ------
// Lanes 0-15 handle edge j, lanes 16-31 edge j+1; each lane loads a 16B
// (8-channel) row slice -> 1.5 LDG/edge. shfl_xor(16) folds the two partial
// sums; lanes 0-15 store the half result row (one uint4 each).
template<int AFF>
__global__ void __launch_bounds__(256) k_gather(int sel,
                                                const float* __restrict__ gamma,
                                                const float* __restrict__ beta)
{
    __shared__ float s_sc[CC], s_sh[CC];
    const int tid  = threadIdx.x;
    const int lane = tid & 31;
    const int sub  = lane & 15;            // channel-group: channels [sub*8, sub*8+8)
    const bool hi  = lane >= 16;

    if (AFF) {
        if (tid < CC) {
            double mean = g_sum[sel][tid]   * (1.0 / NN);
            double var  = g_sumsq[sel][tid] * (1.0 / NN) - mean * mean;
            float sc = gamma[tid] * rsqrtf((float)var + 1e-5f);
            s_sc[tid] = sc;
            s_sh[tid] = beta[tid] - (float)mean * sc;
        }
        __syncthreads();
    }

    int v = blockIdx.x * 8 + (tid >> 5);
    if (v >= NN) return;

    float sc[8], sh[8];
    if (AFF) {
        #pragma unroll
        for (int c = 0; c < 8; c++) { sc[c] = s_sc[sub * 8 + c]; sh[c] = s_sh[sub * 8 + c]; }
    }

    const int start = g_rowstart[v] + g_boff[v >> 8];
    const int deg   = g_cnt[v];
    const int2* __restrict__ ep = g_edge + start;
    const __half* __restrict__ x = g_hx;

    float acc[8];
    #pragma unroll
    for (int c = 0; c < 8; c++) acc[c] = 0.f;

    int j = 0;
    for (; j + 2 <= deg; j += 2) {
        int2 e0 = ep[j];
        int2 e1 = ep[j + 1];
        int   s = hi ? e1.x : e0.x;
        float w = __int_as_float(hi ? e1.y : e0.y);
        uint4 raw = *(const uint4*)(x + (size_t)s * CC + sub * 8);
        float2 f0 = __half22float2(*(__half2*)&raw.x);
        float2 f1 = __half22float2(*(__half2*)&raw.y);
        float2 f2 = __half22float2(*(__half2*)&raw.z);
        float2 f3 = __half22float2(*(__half2*)&raw.w);
        float f[8] = { f0.x, f0.y, f1.x, f1.y, f2.x, f2.y, f3.x, f3.y };
        if (AFF) {
            #pragma unroll
            for (int c = 0; c < 8; c++) f[c] = fmaxf(fmaf(f[c], sc[c], sh[c]), 0.f);
        }
        #pragma unroll
        for (int c = 0; c < 8; c++) acc[c] = fmaf(w, f[c], acc[c]);
    }
    if (j < deg) {   // odd tail: low lanes do the work; hi lanes use w=0
        int2 e0 = ep[j];
        int   s = e0.x;
        float w = hi ? 0.f : __int_as_float(e0.y);
        uint4 raw = *(const uint4*)(x + (size_t)s * CC + sub * 8);
        float2 f0 = __half22float2(*(__half2*)&raw.x);
        float2 f1 = __half22float2(*(__half2*)&raw.y);
        float2 f2 = __half22float2(*(__half2*)&raw.z);
        float2 f3 = __half22float2(*(__half2*)&raw.w);
        float f[8] = { f0.x, f0.y, f1.x, f1.y, f2.x, f2.y, f3.x, f3.y };
        if (AFF) {
            #pragma unroll
            for (int c = 0; c < 8; c++) f[c] = fmaxf(fmaf(f[c], sc[c], sh[c]), 0.f);
        }
        #pragma unroll
        for (int c = 0; c < 8; c++) acc[c] = fmaf(w, f[c], acc[c]);
    }

    #pragma unroll
    for (int c = 0; c < 8; c++)
        acc[c] += __shfl_xor_sync(0xffffffffu, acc[c], 16);

    if (!hi) {
        __half2 h0 = __floats2half2_rn(acc[0], acc[1]);
        __half2 h1 = __floats2half2_rn(acc[2], acc[3]);
        __half2 h2 = __floats2half2_rn(acc[4], acc[5]);
        __half2 h3 = __floats2half2_rn(acc[6], acc[7]);
        uint4 p;
        p.x = *(unsigned*)&h0;  p.y = *(unsigned*)&h1;
        p.z = *(unsigned*)&h2;  p.w = *(unsigned*)&h3;
        *(uint4*)(g_ah + (size_t)v * CC + sub * 8) = p;
    }
}

// ---------------- 128x128 GEMM via wmma (HMMA) with fused BN stats ---------
#define AH_STRIDE 136                       // halfs, padded
#define CS_STRIDE 132                       // floats, padded
#define SMEM_GEMM_BYTES (69632 + 1024)      // Ah(34816)+Bh(34816) ov. Cs(67584); +csum/csq
__global__ void __launch_bounds__(256) k_gemm128(const float* __restrict__ Wg,
                                                 int sel)
{
    extern __shared__ char smraw[];
    __half* Ah   = (__half*)smraw;                    // 128 x 136 halfs
    __half* Bh   = (__half*)(smraw + 34816);          // 128 x 136 halfs
    float*  Cs   = (float*)smraw;                     // 128 x 132 floats (overlay)
    float*  csum = (float*)(smraw + 69632);           // 128
    float*  csq  = csum + 128;                        // 128

    const int tid = threadIdx.x;
    const int wid = tid >> 5;
    const int rowBase = blockIdx.x * 128;

    // load W (row-major [k][c], fp32) -> Bh half
    #pragma unroll
    for (int i = 0; i < 16; i++) {
        int idx = i * 1024 + tid * 4;          // 4 consecutive floats
        int row = idx >> 7;
        int col = idx & 127;
        float4 w4 = *(const float4*)(Wg + idx);
        __half2 h0 = __floats2half2_rn(w4.x, w4.y);
        __half2 h1 = __floats2half2_rn(w4.z, w4.w);
        uint2 p;  p.x = *(unsigned*)&h0;  p.y = *(unsigned*)&h1;
        *(uint2*)(Bh + row * AH_STRIDE + col) = p;
    }
    // load A tile (half rows from g_ah)
    #pragma unroll
    for (int i = 0; i < 16; i++) {
        int fl  = i * 256 + tid;               // uint2 index (4 halfs)
        int row = fl >> 5;
        int q   = fl & 31;
        int grow = rowBase + row;
        uint2 p = make_uint2(0u, 0u);
        if (grow < NN) p = *(const uint2*)(g_ah + (size_t)grow * CC + q * 4);
        *(uint2*)(Ah + row * AH_STRIDE + q * 4) = p;
    }
    if (tid < 128) { csum[tid] = 0.f; csq[tid] = 0.f; }
    __syncthreads();

    // warps: 2 along M (64 rows each), 4 along N (32 cols each)
    const int warp_m = wid & 1;
    const int warp_n = wid >> 1;

    wmma::fragment<wmma::accumulator, 16, 16, 16, float> cfr[4][2];
    #pragma unroll
    for (int i = 0; i < 4; i++)
        #pragma unroll
        for (int j = 0; j < 2; j++) wmma::fill_fragment(cfr[i][j], 0.0f);

    #pragma unroll
    for (int ks = 0; ks < 8; ks++) {
        wmma::fragment<wmma::matrix_a, 16, 16, 16, __half, wmma::row_major> afr[4];
        wmma::fragment<wmma::matrix_b, 16, 16, 16, __half, wmma::row_major> bfr[2];
        #pragma unroll
        for (int i = 0; i < 4; i++)
            wmma::load_matrix_sync(afr[i],
                Ah + (warp_m * 64 + i * 16) * AH_STRIDE + ks * 16, AH_STRIDE);
        #pragma unroll
        for (int j = 0; j < 2; j++)
            wmma::load_matrix_sync(bfr[j],
                Bh + (ks * 16) * AH_STRIDE + warp_n * 32 + j * 16, AH_STRIDE);
        #pragma unroll
        for (int i = 0; i < 4; i++)
            #pragma unroll
            for (int j = 0; j < 2; j++)
                wmma::mma_sync(cfr[i][j], afr[i], bfr[j], cfr[i][j]);
    }
    __syncthreads();   // all warps done reading Ah/Bh before Cs overlay

    #pragma unroll
    for (int i = 0; i < 4; i++)
        #pragma unroll
        for (int j = 0; j < 2; j++)
            wmma::store_matrix_sync(
                Cs + (warp_m * 64 + i * 16) * CS_STRIDE + warp_n * 32 + j * 16,
                cfr[i][j], CS_STRIDE, wmma::mem_row_major);
    __syncthreads();

    // epilogue: h -> g_hx (half) + BN stats, reading Cs
    const int tx = tid & 15;
    const int ty = tid >> 4;
    const int colBase = tx * 8;

    float psum[8], psq[8];
    #pragma unroll
    for (int jj = 0; jj < 8; jj++) { psum[jj] = 0.f; psq[jj] = 0.f; }

    #pragma unroll
    for (int r = 0; r < 8; r++) {
        int row  = ty * 8 + r;
        int grow = rowBase + row;
        if (grow < NN) {
            float4 v0 = *(const float4*)(Cs + row * CS_STRIDE + colBase);
            float4 v1 = *(const float4*)(Cs + row * CS_STRIDE + colBase + 4);
            __half2 h0 = __floats2half2_rn(v0.x, v0.y);
            __half2 h1 = __floats2half2_rn(v0.z, v0.w);
            __half2 h2 = __floats2half2_rn(v1.x, v1.y);
            __half2 h3 = __floats2half2_rn(v1.z, v1.w);
            uint4 p;
            p.x = *(unsigned*)&h0;  p.y = *(unsigned*)&h1;
            p.z = *(unsigned*)&h2;  p.w = *(unsigned*)&h3;
            *(uint4*)(g_hx + (size_t)grow * CC + colBase) = p;
            psum[0] += v0.x;  psq[0] += v0.x * v0.x;
            psum[1] += v0.y;  psq[1] += v0.y * v0.y;
            psum[2] += v0.z;  psq[2] += v0.z * v0.z;
            psum[3] += v0.w;  psq[3] += v0.w * v0.w;
            psum[4] += v1.x;  psq[4] += v1.x * v1.x;
            psum[5] += v1.y;  psq[5] += v1.y * v1.y;
            psum[6] += v1.z;  psq[6] += v1.z * v1.z;
            psum[7] += v1.w;  psq[7] += v1.w * v1.w;
        }
    }
    #pragma unroll
    for (int jj = 0; jj < 8; jj++) {
        atomicAdd(&csum[colBase + jj], psum[jj]);
        atomicAdd(&csq[colBase + jj],  psq[jj]);
    }
    __syncthreads();
    if (tid < 128) {
        atomicAdd(&g_sum[sel][tid],   (double)csum[tid]);
        atomicAdd(&g_sumsq[sel][tid], (double)csq[tid]);
    }
}

// ---------------- layer-3 pre-transform via wmma: z = relu(bn2(h)) @ W3 ----
#define PW_BSTRIDE 56          // halfs
#define PW_CSTRIDE 52          // floats
#define SMEM_PRE_BYTES (34816 + 14336 + 26624)   // Ah + Bw + Cs = 75776
__global__ void __launch_bounds__(256) k_pre(const float* __restrict__ W3,
                                             const float* __restrict__ gamma,
                                             const float* __restrict__ beta)
{
    extern __shared__ char smraw[];
    __half* Ah = (__half*)smraw;                  // 128 x 136 halfs
    __half* Bw = (__half*)(smraw + 34816);        // 128 x 56 halfs (zero-padded)
    float*  Cs = (float*)(smraw + 49152);         // 128 x 52 floats
    __shared__ float s_sc[CC], s_sh[CC];

    const int tid = threadIdx.x;
    const int wid = tid >> 5;
    const int rowBase = blockIdx.x * 128;

    if (tid < CC) {
        double mean = g_sum[1][tid]   * (1.0 / NN);
        double var  = g_sumsq[1][tid] * (1.0 / NN) - mean * mean;
        float sc = gamma[tid] * rsqrtf((float)var + 1e-5f);
        s_sc[tid] = sc;
        s_sh[tid] = beta[tid] - (float)mean * sc;
    }
    // zero Bw (padding cols must be 0)
    for (int i = tid; i < 128 * PW_BSTRIDE / 2; i += 256)
        ((unsigned*)Bw)[i] = 0u;
    __syncthreads();

    // fill Bw from W3 [128 x 40] fp32
    for (int i = tid; i < 5120; i += 256) {
        int row = i / 40, col = i - row * 40;
        Bw[row * PW_BSTRIDE + col] = __float2half_rn(W3[i]);
    }
    // build A tile: relu(bn2(h)) -> half
    #pragma unroll
    for (int i = 0; i < 16; i++) {
        int fl  = i * 256 + tid;       // uint2 index within tile
        int row = fl >> 5;
        int q   = fl & 31;             // 4-channel group
        int grow = rowBase + row;
        uint2 p = make_uint2(0u, 0u);
        if (grow < NN) {
            uint2 raw = *(const uint2*)(g_hx + (size_t)grow * CC + q * 4);
            float2 a = __half22float2(*(__half2*)&raw.x);
            float2 b = __half22float2(*(__half2*)&raw.y);
            float f0 = fmaxf(fmaf(a.x, s_sc[q * 4 + 0], s_sh[q * 4 + 0]), 0.f);
            float f1 = fmaxf(fmaf(a.y, s_sc[q * 4 + 1], s_sh[q * 4 + 1]), 0.f);
            float f2 = fmaxf(fmaf(b.x, s_sc[q * 4 + 2], s_sh[q * 4 + 2]), 0.f);
            float f3 = fmaxf(fmaf(b.y, s_sc[q * 4 + 3], s_sh[q * 4 + 3]), 0.f);
            __half2 h0 = __floats2half2_rn(f0, f1);
            __half2 h1 = __floats2half2_rn(f2, f3);
            p.x = *(unsigned*)&h0;  p.y = *(unsigned*)&h1;
        }
        *(uint2*)(Ah + row * AH_STRIDE + q * 4) = p;
    }
    __syncthreads();

    // wmma: warp w handles rows [w*16, w*16+16), all 48 cols (3 fragments)
    wmma::fragment<wmma::accumulator, 16, 16, 16, float> cfr[3];
    #pragma unroll
    for (int j = 0; j < 3; j++) wmma::fill_fragment(cfr[j], 0.0f);

    #pragma unroll
    for (int ks = 0; ks < 8; ks++) {
        wmma::fragment<wmma::matrix_a, 16, 16, 16, __half, wmma::row_major> afr;
        wmma::load_matrix_sync(afr, Ah + (wid * 16) * AH_STRIDE + ks * 16, AH_STRIDE);
        #pragma unroll
        for (int j = 0; j < 3; j++) {
            wmma::fragment<wmma::matrix_b, 16, 16, 16, __half, wmma::row_major> bfr;
            wmma::load_matrix_sync(bfr, Bw + (ks * 16) * PW_BSTRIDE + j * 16, PW_BSTRIDE);
            wmma::mma_sync(cfr[j], afr, bfr, cfr[j]);
        }
    }
    #pragma unroll
    for (int j = 0; j < 3; j++)
        wmma::store_matrix_sync(Cs + (wid * 16) * PW_CSTRIDE + j * 16,
                                cfr[j], PW_CSTRIDE, wmma::mem_row_major);
    __syncthreads();

    // epilogue: thread t -> row t/2, cols (t&1)*20 .. +20, write half z
    {
        int row  = tid >> 1;
        int c0   = (tid & 1) * 20;
        int grow = rowBase + row;
        if (grow < NN) {
            const float* cr = Cs + row * PW_CSTRIDE + c0;
            __half* zr = g_zh + (size_t)grow * 40 + c0;
            #pragma unroll
            for (int c = 0; c < 20; c += 2) {
                __half2 h = __floats2half2_rn(cr[c], cr[c + 1]);
                *(unsigned*)(zr + c) = *(unsigned*)&h;
            }
        }
    }
}

// ---------------- layer-3 aggregation over 40 half channels, + bias --------
__global__ void __launch_bounds__(256) k_gather_out(const float* __restrict__ b3,
                                                    float* __restrict__ out)
{
    int v = blockIdx.x * 8 + (threadIdx.x >> 5);
    if (v >= NN) return;
    const int lane = threadIdx.x & 31;

    const int start = g_rowstart[v] + g_boff[v >> 8];
    const int deg   = g_cnt[v];
    const int2* __restrict__ ep = g_edge + start;
    const __half* __restrict__ z = g_zh;

    float2 acc = make_float2(0.f, 0.f);
    for (int j = 0; j < deg; j++) {
        int2  e  = ep[j];
        float w0 = __int_as_float(e.y);
        if (lane < 20) {
            unsigned raw = *(const unsigned*)(z + (size_t)e.x * 40 + lane * 2);
            float2 zz = __half22float2(*(__half2*)&raw);
            acc.x = fmaf(w0, zz.x, acc.x);
            acc.y = fmaf(w0, zz.y, acc.y);
        }
    }
    if (lane < 20) {
        float2 bb = *(const float2*)(b3 + lane * 2);
        float2 o;
        o.x = acc.x + bb.x;
        o.y = acc.y + bb.y;
        *(float2*)(out + (size_t)v * 40 + lane * 2) = o;
    }
}

// ---------------- launch ---------------------------------------------------
extern "C" void kernel_launch(void* const* d_in, const int* in_sizes, int n_in,
                              void* d_out, int out_size)
{
    const float* feat   = (const float*)d_in[0];
    const int*   src    = (const int*)  d_in[1];
    const int*   dst    = (const int*)  d_in[2];
    const float* ew     = (const float*)d_in[3];
    const float* W1     = (const float*)d_in[4];
    const float* W2     = (const float*)d_in[5];
    const float* W3     = (const float*)d_in[6];
    const float* b3     = (const float*)d_in[7];
    const float* gamma1 = (const float*)d_in[8];
    const float* beta1  = (const float*)d_in[9];
    const float* gamma2 = (const float*)d_in[10];
    const float* beta2  = (const float*)d_in[11];
    float* out = (float*)d_out;
    const int E = in_sizes[1];

    cudaFuncSetAttribute(k_gemm128, cudaFuncAttributeMaxDynamicSharedMemorySize, SMEM_GEMM_BYTES);
    cudaFuncSetAttribute(k_pre,     cudaFuncAttributeMaxDynamicSharedMemorySize, SMEM_PRE_BYTES);

    const int egrid = (E + 255) / 256;
    const int ggrid = (NN + 127) / 128;
    const int agrid = (NN + 7) / 8;
    const int cgrid = (NN * (CC / 4) + 255) / 256;

    // ---- CSR build ----
    k_cvt  <<<cgrid, 256>>>(feat);
    k_hist <<<egrid, 256>>>(dst, E);
    k_scan1<<<NB, 256>>>();
    k_scan2<<<1, 512>>>();
    k_fill <<<egrid, 256>>>(src, dst, ew, E);

    // ---- layer 1 ----
    k_gather<0><<<agrid, 256>>>(0, nullptr, nullptr);
    k_gemm128<<<ggrid, 256, SMEM_GEMM_BYTES>>>(W1, 0);

    // ---- layer 2 (BN1+ReLU fused into gather) ----
    k_gather<1><<<agrid, 256>>>(0, gamma1, beta1);
    k_gemm128<<<ggrid, 256, SMEM_GEMM_BYTES>>>(W2, 1);

    // ---- layer 3: wmma pre-transform (BN2+ReLU+W3), then 40-ch gather ----
    k_pre<<<ggrid, 256, SMEM_PRE_BYTES>>>(W3, gamma2, beta2);
    k_gather_out<<<agrid, 256>>>(b3, out);
}

// round 16
// speedup vs baseline: 1.1481x; 1.1481x over previous
#include <cuda_runtime.h>
#include <cuda_fp16.h>
#include <mma.h>
#include <cstdint>

using namespace nvcuda;

#define NN   100000
#define CC   128
#define EMAX 1600000
#define NB   ((NN + 255) / 256)        // 391 scan blocks

// ---------------- scratch (static device globals) --------------------------
__device__ __align__(16) __half g_ah[(size_t)NN * CC];   // half agg buffer
__device__ __align__(16) __half g_zh[(size_t)NN * 40];   // layer-3 z (half)
__device__ __align__(16) __half g_hx[(size_t)NN * CC];   // half features
__device__ int   g_cnt[NN];
__device__ int   g_rowstart[NN];       // block-local exclusive prefix
__device__ int   g_cursor[NN];         // fill counters (zeroed in k_cvt)
__device__ int   g_bsum[NB];
__device__ int   g_boff[NB];           // block offsets (exclusive)
__device__ int   g_psrc[EMAX];
__device__ float g_pw[EMAX];
__device__ double g_sum[2][CC];
__device__ double g_sumsq[2][CC];

// ---------------- merged init + feat->half conversion ----------------------
__global__ void __launch_bounds__(256) k_cvt(const float* __restrict__ feat)
{
    size_t i = (size_t)blockIdx.x * 256 + threadIdx.x;   // float4 index
    if (i < (size_t)NN * (CC / 4)) {
        float4 v = ((const float4*)feat)[i];
        __half2 h0 = __floats2half2_rn(v.x, v.y);
        __half2 h1 = __floats2half2_rn(v.z, v.w);
        uint2 p;
        p.x = *(unsigned*)&h0;
        p.y = *(unsigned*)&h1;
        ((uint2*)g_hx)[i] = p;
    }
    int j = blockIdx.x * 256 + threadIdx.x;
    if (j < NN) { g_cnt[j] = 0; g_cursor[j] = 0; }
    if (blockIdx.x == 0 && threadIdx.x < CC) {
        g_sum[0][threadIdx.x] = 0.0;  g_sumsq[0][threadIdx.x] = 0.0;
        g_sum[1][threadIdx.x] = 0.0;  g_sumsq[1][threadIdx.x] = 0.0;
    }
}

__global__ void __launch_bounds__(256) k_hist(const int* __restrict__ dst, int E)
{
    int e = blockIdx.x * 256 + threadIdx.x;
    if (e < E) atomicAdd(&g_cnt[dst[e]], 1);
}

__global__ void __launch_bounds__(256) k_scan1()
{
    __shared__ int sm[256];
    int tid = threadIdx.x;
    int i = blockIdx.x * 256 + tid;
    int c = (i < NN) ? g_cnt[i] : 0;
    sm[tid] = c;
    __syncthreads();
    #pragma unroll
    for (int off = 1; off < 256; off <<= 1) {
        int v = (tid >= off) ? sm[tid - off] : 0;
        __syncthreads();
        sm[tid] += v;
        __syncthreads();
    }
    if (i < NN) g_rowstart[i] = sm[tid] - c;       // block-LOCAL exclusive
    if (tid == 255) g_bsum[blockIdx.x] = sm[255];
}

__global__ void __launch_bounds__(512) k_scan2()
{
    __shared__ int sm[512];
    int tid = threadIdx.x;
    int v = (tid < NB) ? g_bsum[tid] : 0;
    sm[tid] = v;
    __syncthreads();
    #pragma unroll
    for (int off = 1; off < 512; off <<= 1) {
        int u = (tid >= off) ? sm[tid - off] : 0;
        __syncthreads();
        sm[tid] += u;
        __syncthreads();
    }
    if (tid < NB) g_boff[tid] = sm[tid] - v;       // exclusive block offset
}

__global__ void __launch_bounds__(256) k_fill(const int* __restrict__ src,
                                              const int* __restrict__ dst,
                                              const float* __restrict__ ew,
                                              int E)
{
    int e = blockIdx.x * 256 + threadIdx.x;
    if (e < E) {
        int d = dst[e];
        int base = g_rowstart[d] + g_boff[d >> 8];
        int slot = base + atomicAdd(&g_cursor[d], 1);
        g_psrc[slot] = src[e];
        g_pw[slot]   = ew[e];
    }
}

// ---------------- gather aggregation: warp per node ------------------------
// fp32 accumulation, single rounding to half on store into g_ah.
// (Round-14 form — empirically optimal; batch-4, lane-split, and fused
//  variants all regressed.)
template<int AFF>
__global__ void __launch_bounds__(256) k_gather(int sel,
                                                const float* __restrict__ gamma,
                                                const float* __restrict__ beta)
{
    __shared__ float s_sc[CC], s_sh[CC];
    const int tid  = threadIdx.x;
    const int lane = tid & 31;

    if (AFF) {
        if (tid < CC) {
            double mean = g_sum[sel][tid]   * (1.0 / NN);
            double var  = g_sumsq[sel][tid] * (1.0 / NN) - mean * mean;
            float sc = gamma[tid] * rsqrtf((float)var + 1e-5f);
            s_sc[tid] = sc;
            s_sh[tid] = beta[tid] - (float)mean * sc;
        }
        __syncthreads();
    }

    int v = blockIdx.x * 8 + (tid >> 5);
    if (v >= NN) return;

    float4 sc4, sh4;
    if (AFF) {
        sc4 = *(const float4*)(s_sc + lane * 4);
        sh4 = *(const float4*)(s_sh + lane * 4);
    }

    const int start = g_rowstart[v] + g_boff[v >> 8];
    const int deg   = g_cnt[v];
    float4 acc = make_float4(0.f, 0.f, 0.f, 0.f);
    const __half* __restrict__ x = g_hx;

    for (int j = 0; j < deg; j++) {
        int   s0 = g_psrc[start + j];
        float w0 = g_pw[start + j];
        uint2 raw = *(const uint2*)(x + (size_t)s0 * CC + lane * 4);
        float2 f0 = __half22float2(*(__half2*)&raw.x);
        float2 f1 = __half22float2(*(__half2*)&raw.y);
        if (AFF) {
            f0.x = fmaxf(fmaf(f0.x, sc4.x, sh4.x), 0.f);
            f0.y = fmaxf(fmaf(f0.y, sc4.y, sh4.y), 0.f);
            f1.x = fmaxf(fmaf(f1.x, sc4.z, sh4.z), 0.f);
            f1.y = fmaxf(fmaf(f1.y, sc4.w, sh4.w), 0.f);
        }
        acc.x = fmaf(w0, f0.x, acc.x);
        acc.y = fmaf(w0, f0.y, acc.y);
        acc.z = fmaf(w0, f1.x, acc.z);
        acc.w = fmaf(w0, f1.y, acc.w);
    }
    __half2 o0 = __floats2half2_rn(acc.x, acc.y);
    __half2 o1 = __floats2half2_rn(acc.z, acc.w);
    uint2 p;
    p.x = *(unsigned*)&o0;
    p.y = *(unsigned*)&o1;
    *(uint2*)(g_ah + (size_t)v * CC + lane * 4) = p;
}

// ---------------- 128x128 GEMM via wmma (HMMA) with fused BN stats ---------
#define AH_STRIDE 136                       // halfs, padded
#define CS_STRIDE 132                       // floats, padded
#define SMEM_GEMM_BYTES (69632 + 1024)      // Ah(34816)+Bh(34816) ov. Cs(67584); +csum/csq
__global__ void __launch_bounds__(256) k_gemm128(const float* __restrict__ Wg,
                                                 int sel)
{
    extern __shared__ char smraw[];
    __half* Ah   = (__half*)smraw;                    // 128 x 136 halfs
    __half* Bh   = (__half*)(smraw + 34816);          // 128 x 136 halfs
    float*  Cs   = (float*)smraw;                     // 128 x 132 floats (overlay)
    float*  csum = (float*)(smraw + 69632);           // 128
    float*  csq  = csum + 128;                        // 128

    const int tid = threadIdx.x;
    const int wid = tid >> 5;
    const int rowBase = blockIdx.x * 128;

    // load W (row-major [k][c], fp32) -> Bh half
    #pragma unroll
    for (int i = 0; i < 16; i++) {
        int idx = i * 1024 + tid * 4;          // 4 consecutive floats
        int row = idx >> 7;
        int col = idx & 127;
        float4 w4 = *(const float4*)(Wg + idx);
        __half2 h0 = __floats2half2_rn(w4.x, w4.y);
        __half2 h1 = __floats2half2_rn(w4.z, w4.w);
        uint2 p;  p.x = *(unsigned*)&h0;  p.y = *(unsigned*)&h1;
        *(uint2*)(Bh + row * AH_STRIDE + col) = p;
    }
    // load A tile (half rows from g_ah)
    #pragma unroll
    for (int i = 0; i < 16; i++) {
        int fl  = i * 256 + tid;               // uint2 index (4 halfs)
        int row = fl >> 5;
        int q   = fl & 31;
        int grow = rowBase + row;
        uint2 p = make_uint2(0u, 0u);
        if (grow < NN) p = *(const uint2*)(g_ah + (size_t)grow * CC + q * 4);
        *(uint2*)(Ah + row * AH_STRIDE + q * 4) = p;
    }
    if (tid < 128) { csum[tid] = 0.f; csq[tid] = 0.f; }
    __syncthreads();

    // warps: 2 along M (64 rows each), 4 along N (32 cols each)
    const int warp_m = wid & 1;
    const int warp_n = wid >> 1;

    wmma::fragment<wmma::accumulator, 16, 16, 16, float> cfr[4][2];
    #pragma unroll
    for (int i = 0; i < 4; i++)
        #pragma unroll
        for (int j = 0; j < 2; j++) wmma::fill_fragment(cfr[i][j], 0.0f);

    #pragma unroll
    for (int ks = 0; ks < 8; ks++) {
        wmma::fragment<wmma::matrix_a, 16, 16, 16, __half, wmma::row_major> afr[4];
        wmma::fragment<wmma::matrix_b, 16, 16, 16, __half, wmma::row_major> bfr[2];
        #pragma unroll
        for (int i = 0; i < 4; i++)
            wmma::load_matrix_sync(afr[i],
                Ah + (warp_m * 64 + i * 16) * AH_STRIDE + ks * 16, AH_STRIDE);
        #pragma unroll
        for (int j = 0; j < 2; j++)
            wmma::load_matrix_sync(bfr[j],
                Bh + (ks * 16) * AH_STRIDE + warp_n * 32 + j * 16, AH_STRIDE);
        #pragma unroll
        for (int i = 0; i < 4; i++)
            #pragma unroll
            for (int j = 0; j < 2; j++)
                wmma::mma_sync(cfr[i][j], afr[i], bfr[j], cfr[i][j]);
    }
    __syncthreads();   // all warps done reading Ah/Bh before Cs overlay

    #pragma unroll
    for (int i = 0; i < 4; i++)
        #pragma unroll
        for (int j = 0; j < 2; j++)
            wmma::store_matrix_sync(
                Cs + (warp_m * 64 + i * 16) * CS_STRIDE + warp_n * 32 + j * 16,
                cfr[i][j], CS_STRIDE, wmma::mem_row_major);
    __syncthreads();

    // epilogue: h -> g_hx (half) + BN stats, reading Cs
    const int tx = tid & 15;
    const int ty = tid >> 4;
    const int colBase = tx * 8;

    float psum[8], psq[8];
    #pragma unroll
    for (int jj = 0; jj < 8; jj++) { psum[jj] = 0.f; psq[jj] = 0.f; }

    #pragma unroll
    for (int r = 0; r < 8; r++) {
        int row  = ty * 8 + r;
        int grow = rowBase + row;
        if (grow < NN) {
            float4 v0 = *(const float4*)(Cs + row * CS_STRIDE + colBase);
            float4 v1 = *(const float4*)(Cs + row * CS_STRIDE + colBase + 4);
            __half2 h0 = __floats2half2_rn(v0.x, v0.y);
            __half2 h1 = __floats2half2_rn(v0.z, v0.w);
            __half2 h2 = __floats2half2_rn(v1.x, v1.y);
            __half2 h3 = __floats2half2_rn(v1.z, v1.w);
            uint4 p;
            p.x = *(unsigned*)&h0;  p.y = *(unsigned*)&h1;
            p.z = *(unsigned*)&h2;  p.w = *(unsigned*)&h3;
            *(uint4*)(g_hx + (size_t)grow * CC + colBase) = p;
            psum[0] += v0.x;  psq[0] += v0.x * v0.x;
            psum[1] += v0.y;  psq[1] += v0.y * v0.y;
            psum[2] += v0.z;  psq[2] += v0.z * v0.z;
            psum[3] += v0.w;  psq[3] += v0.w * v0.w;
            psum[4] += v1.x;  psq[4] += v1.x * v1.x;
            psum[5] += v1.y;  psq[5] += v1.y * v1.y;
            psum[6] += v1.z;  psq[6] += v1.z * v1.z;
            psum[7] += v1.w;  psq[7] += v1.w * v1.w;
        }
    }
    #pragma unroll
    for (int jj = 0; jj < 8; jj++) {
        atomicAdd(&csum[colBase + jj], psum[jj]);
        atomicAdd(&csq[colBase + jj],  psq[jj]);
    }
    __syncthreads();
    if (tid < 128) {
        atomicAdd(&g_sum[sel][tid],   (double)csum[tid]);
        atomicAdd(&g_sumsq[sel][tid], (double)csq[tid]);
    }
}

// ---------------- layer-3 pre-transform via wmma: z = relu(bn2(h)) @ W3 ----
#define PW_BSTRIDE 56          // halfs
#define PW_CSTRIDE 52          // floats
#define SMEM_PRE_BYTES (34816 + 14336 + 26624)   // Ah + Bw + Cs = 75776
__global__ void __launch_bounds__(256) k_pre(const float* __restrict__ W3,
                                             const float* __restrict__ gamma,
                                             const float* __restrict__ beta)
{
    extern __shared__ char smraw[];
    __half* Ah = (__half*)smraw;                  // 128 x 136 halfs
    __half* Bw = (__half*)(smraw + 34816);        // 128 x 56 halfs (zero-padded)
    float*  Cs = (float*)(smraw + 49152);         // 128 x 52 floats
    __shared__ float s_sc[CC], s_sh[CC];

    const int tid = threadIdx.x;
    const int wid = tid >> 5;
    const int rowBase = blockIdx.x * 128;

    if (tid < CC) {
        double mean = g_sum[1][tid]   * (1.0 / NN);
        double var  = g_sumsq[1][tid] * (1.0 / NN) - mean * mean;
        float sc = gamma[tid] * rsqrtf((float)var + 1e-5f);
        s_sc[tid] = sc;
        s_sh[tid] = beta[tid] - (float)mean * sc;
    }
    // zero Bw (padding cols must be 0)
    for (int i = tid; i < 128 * PW_BSTRIDE / 2; i += 256)
        ((unsigned*)Bw)[i] = 0u;
    __syncthreads();

    // fill Bw from W3 [128 x 40] fp32
    for (int i = tid; i < 5120; i += 256) {
        int row = i / 40, col = i - row * 40;
        Bw[row * PW_BSTRIDE + col] = __float2half_rn(W3[i]);
    }
    // build A tile: relu(bn2(h)) -> half
    #pragma unroll
    for (int i = 0; i < 16; i++) {
        int fl  = i * 256 + tid;       // uint2 index within tile
        int row = fl >> 5;
        int q   = fl & 31;             // 4-channel group
        int grow = rowBase + row;
        uint2 p = make_uint2(0u, 0u);
        if (grow < NN) {
            uint2 raw = *(const uint2*)(g_hx + (size_t)grow * CC + q * 4);
            float2 a = __half22float2(*(__half2*)&raw.x);
            float2 b = __half22float2(*(__half2*)&raw.y);
            float f0 = fmaxf(fmaf(a.x, s_sc[q * 4 + 0], s_sh[q * 4 + 0]), 0.f);
            float f1 = fmaxf(fmaf(a.y, s_sc[q * 4 + 1], s_sh[q * 4 + 1]), 0.f);
            float f2 = fmaxf(fmaf(b.x, s_sc[q * 4 + 2], s_sh[q * 4 + 2]), 0.f);
            float f3 = fmaxf(fmaf(b.y, s_sc[q * 4 + 3], s_sh[q * 4 + 3]), 0.f);
            __half2 h0 = __floats2half2_rn(f0, f1);
            __half2 h1 = __floats2half2_rn(f2, f3);
            p.x = *(unsigned*)&h0;  p.y = *(unsigned*)&h1;
        }
        *(uint2*)(Ah + row * AH_STRIDE + q * 4) = p;
    }
    __syncthreads();

    // wmma: warp w handles rows [w*16, w*16+16), all 48 cols (3 fragments)
    wmma::fragment<wmma::accumulator, 16, 16, 16, float> cfr[3];
    #pragma unroll
    for (int j = 0; j < 3; j++) wmma::fill_fragment(cfr[j], 0.0f);

    #pragma unroll
    for (int ks = 0; ks < 8; ks++) {
        wmma::fragment<wmma::matrix_a, 16, 16, 16, __half, wmma::row_major> afr;
        wmma::load_matrix_sync(afr, Ah + (wid * 16) * AH_STRIDE + ks * 16, AH_STRIDE);
        #pragma unroll
        for (int j = 0; j < 3; j++) {
            wmma::fragment<wmma::matrix_b, 16, 16, 16, __half, wmma::row_major> bfr;
            wmma::load_matrix_sync(bfr, Bw + (ks * 16) * PW_BSTRIDE + j * 16, PW_BSTRIDE);
            wmma::mma_sync(cfr[j], afr, bfr, cfr[j]);
        }
    }
    #pragma unroll
    for (int j = 0; j < 3; j++)
        wmma::store_matrix_sync(Cs + (wid * 16) * PW_CSTRIDE + j * 16,
                                cfr[j], PW_CSTRIDE, wmma::mem_row_major);
    __syncthreads();

    // epilogue: thread t -> row t/2, cols (t&1)*20 .. +20, write half z
    {
        int row  = tid >> 1;
        int c0   = (tid & 1) * 20;
        int grow = rowBase + row;
        if (grow < NN) {
            const float* cr = Cs + row * PW_CSTRIDE + c0;
            __half* zr = g_zh + (size_t)grow * 40 + c0;
            #pragma unroll
            for (int c = 0; c < 20; c += 2) {
                __half2 h = __floats2half2_rn(cr[c], cr[c + 1]);
                *(unsigned*)(zr + c) = *(unsigned*)&h;
            }
        }
    }
}

// ---------------- layer-3 aggregation over 40 half channels, + bias --------
__global__ void __launch_bounds__(256) k_gather_out(const float* __restrict__ b3,
                                                    float* __restrict__ out)
{
    int v = blockIdx.x * 8 + (threadIdx.x >> 5);
    if (v >= NN) return;
    const int lane = threadIdx.x & 31;

    const int start = g_rowstart[v] + g_boff[v >> 8];
    const int deg   = g_cnt[v];
    const __half* __restrict__ z = g_zh;

    float2 acc = make_float2(0.f, 0.f);
    for (int j = 0; j < deg; j++) {
        int   s0 = g_psrc[start + j];
        float w0 = g_pw[start + j];
        if (lane < 20) {
            unsigned raw = *(const unsigned*)(z + (size_t)s0 * 40 + lane * 2);
            float2 zz = __half22float2(*(__half2*)&raw);
            acc.x = fmaf(w0, zz.x, acc.x);
            acc.y = fmaf(w0, zz.y, acc.y);
        }
    }
    if (lane < 20) {
        float2 bb = *(const float2*)(b3 + lane * 2);
        float2 o;
        o.x = acc.x + bb.x;
        o.y = acc.y + bb.y;
        *(float2*)(out + (size_t)v * 40 + lane * 2) = o;
    }
}

// ---------------- launch ---------------------------------------------------
extern "C" void kernel_launch(void* const* d_in, const int* in_sizes, int n_in,
                              void* d_out, int out_size)
{
    const float* feat   = (const float*)d_in[0];
    const int*   src    = (const int*)  d_in[1];
    const int*   dst    = (const int*)  d_in[2];
    const float* ew     = (const float*)d_in[3];
    const float* W1     = (const float*)d_in[4];
    const float* W2     = (const float*)d_in[5];
    const float* W3     = (const float*)d_in[6];
    const float* b3     = (const float*)d_in[7];
    const float* gamma1 = (const float*)d_in[8];
    const float* beta1  = (const float*)d_in[9];
    const float* gamma2 = (const float*)d_in[10];
    const float* beta2  = (const float*)d_in[11];
    float* out = (float*)d_out;
    const int E = in_sizes[1];

    cudaFuncSetAttribute(k_gemm128, cudaFuncAttributeMaxDynamicSharedMemorySize, SMEM_GEMM_BYTES);
    cudaFuncSetAttribute(k_pre,     cudaFuncAttributeMaxDynamicSharedMemorySize, SMEM_PRE_BYTES);

    const int egrid = (E + 255) / 256;
    const int ggrid = (NN + 127) / 128;
    const int agrid = (NN + 7) / 8;
    const int cgrid = (NN * (CC / 4) + 255) / 256;

    // ---- CSR build ----
    k_cvt  <<<cgrid, 256>>>(feat);
    k_hist <<<egrid, 256>>>(dst, E);
    k_scan1<<<NB, 256>>>();
    k_scan2<<<1, 512>>>();
    k_fill <<<egrid, 256>>>(src, dst, ew, E);

    // ---- layer 1 ----
    k_gather<0><<<agrid, 256>>>(0, nullptr, nullptr);
    k_gemm128<<<ggrid, 256, SMEM_GEMM_BYTES>>>(W1, 0);

    // ---- layer 2 (BN1+ReLU fused into gather) ----
    k_gather<1><<<agrid, 256>>>(0, gamma1, beta1);
    k_gemm128<<<ggrid, 256, SMEM_GEMM_BYTES>>>(W2, 1);

    // ---- layer 3: wmma pre-transform (BN2+ReLU+W3), then 40-ch gather ----
    k_pre<<<ggrid, 256, SMEM_PRE_BYTES>>>(W3, gamma2, beta2);
    k_gather_out<<<agrid, 256>>>(b3, out);
}